// round 16
// baseline (speedup 1.0000x reference)
#include <cuda_runtime.h>
#include <cstdint>

#define FEAT 128          // output feature dim
#define HF   256          // num_heads * feat_dim (accumulator width)
#define MAX_NODES 50000
#define MAX_EDGES 1000000

// Binning scratch (no g_acc anymore — gather is fused into the GEMM kernel)
__device__ int g_cnt[MAX_NODES];        // per-node edge count (rebuilt each replay)
__device__ int g_off[MAX_NODES + 1];    // exclusive offsets
__device__ int g_cur[MAX_NODES];        // running fill cursor
__device__ int g_eids[MAX_EDGES];       // edge ids bucketed by dst

// ---------------------------------------------------------------------------
// Kernel 0: zero per-node counters
// ---------------------------------------------------------------------------
__global__ void zero_cnt_kernel(int n_nodes) {
    int i = blockIdx.x * blockDim.x + threadIdx.x;
    if (i < n_nodes) g_cnt[i] = 0;
}

// ---------------------------------------------------------------------------
// Kernel 1: histogram of destinations
// ---------------------------------------------------------------------------
__global__ void hist_kernel(const int* __restrict__ nbrs, int n_edges, int n_nodes) {
    int e = blockIdx.x * blockDim.x + threadIdx.x;
    if (e >= n_edges) return;
    int dst = __ldg(nbrs + 2 * e);
    if ((unsigned)dst < (unsigned)n_nodes)
        atomicAdd(&g_cnt[dst], 1);
}

// ---------------------------------------------------------------------------
// Kernel 2: exclusive scan over g_cnt -> g_off, g_cur  (single block, 1024 thr)
// ---------------------------------------------------------------------------
__global__ void scan_kernel(int n_nodes) {
    __shared__ int part[1024];
    const int tid = threadIdx.x;
    const int per = (n_nodes + 1023) / 1024;
    const int start = tid * per;
    const int stop  = min(start + per, n_nodes);

    int s = 0;
    for (int i = start; i < stop; ++i) s += g_cnt[i];
    part[tid] = s;
    __syncthreads();

    // Hillis-Steele inclusive scan (read-all, sync, write-all)
    for (int d = 1; d < 1024; d <<= 1) {
        int v = (tid >= d) ? part[tid - d] : 0;
        __syncthreads();
        part[tid] += v;
        __syncthreads();
    }

    int run = (tid == 0) ? 0 : part[tid - 1];
    for (int i = start; i < stop; ++i) {
        g_off[i] = run;
        g_cur[i] = run;
        run += g_cnt[i];
    }
    if (tid == 1023) g_off[n_nodes] = part[1023];
}

// ---------------------------------------------------------------------------
// Kernel 3: fill buckets with edge ids
// ---------------------------------------------------------------------------
__global__ void fill_kernel(const int* __restrict__ nbrs, int n_edges, int n_nodes) {
    int e = blockIdx.x * blockDim.x + threadIdx.x;
    if (e >= n_edges) return;
    int dst = __ldg(nbrs + 2 * e);
    if ((unsigned)dst >= (unsigned)n_nodes) return;
    int pos = atomicAdd(&g_cur[dst], 1);
    g_eids[pos] = e;
}

// ---------------------------------------------------------------------------
// Kernel 4 (fused): gather per-node message sums + GEMM + residual
//   out[n, j] = x_i[n, j] + b[j] + sum_k acc[n, k] * W[j, k]
// Block: 256 threads, 64 nodes.
//   Gather: 64 threads per node (one float4 slot each) walk the node's edge
//   bucket, accumulate in registers, store once to smem acc tile.
//   GEMM: sW[k4][j] transposed, row stride 129 f4 (conflict-free); thread
//   (tx=tid&15, ty=tid>>4) computes 4 nodes x 8 outputs.
// ---------------------------------------------------------------------------
#define TILE_M 64
#define SW_STRIDE 129   // float4 units per k4-row of sW

__global__ void fused_gemm_kernel(const float* __restrict__ scaled_v,
                                  const float* __restrict__ x_i,
                                  const float* __restrict__ W,
                                  const float* __restrict__ b,
                                  float*       __restrict__ out,
                                  int n_nodes) {
    extern __shared__ float4 smem[];
    float4* sW = smem;                       // [64][SW_STRIDE]
    float4* sA = smem + 64 * SW_STRIDE;      // [TILE_M][64]

    const int tid = threadIdx.x;
    const int node0 = blockIdx.x * TILE_M;

    // --- Load W (8192 float4) transposed: sW[k4][j] = W4[j*64 + k4] ---
    const float4* W4 = reinterpret_cast<const float4*>(W);
    #pragma unroll
    for (int it = 0; it < 32; ++it) {
        int g = tid + it * 256;              // coalesced global read
        int j  = g >> 6;
        int k4 = g & 63;
        sW[k4 * SW_STRIDE + j] = __ldg(W4 + g);
    }

    // --- Gather: sum scaled_v rows for each node in the tile ---
    const float4* sv4 = reinterpret_cast<const float4*>(scaled_v);
    const int slot = tid & 63;               // float4 lane within 1KB row
    const int sub  = tid >> 6;               // 0..3: which node of the group
    #pragma unroll
    for (int ng = 0; ng < 16; ++ng) {
        int n_local = ng * 4 + sub;
        int node = node0 + n_local;
        float4 acc = make_float4(0.f, 0.f, 0.f, 0.f);
        if (node < n_nodes) {
            int beg = __ldg(&g_off[node]);
            int end = __ldg(&g_off[node + 1]);
            #pragma unroll 4
            for (int t = beg; t < end; ++t) {
                int e = __ldg(&g_eids[t]);   // broadcast within warp
                float4 v = __ldg(sv4 + (size_t)e * 64 + slot);
                acc.x += v.x; acc.y += v.y; acc.z += v.z; acc.w += v.w;
            }
        }
        sA[n_local * 64 + slot] = acc;
    }
    __syncthreads();

    // --- GEMM ---
    const int tx = tid & 15;     // j = tx + 16*jj
    const int ty = tid >> 4;     // node = node0 + ty*4 + i

    float c[4][8];
    #pragma unroll
    for (int i = 0; i < 4; ++i)
        #pragma unroll
        for (int jj = 0; jj < 8; ++jj) c[i][jj] = 0.f;

    #pragma unroll 4
    for (int k4 = 0; k4 < 64; ++k4) {
        float4 a[4];
        #pragma unroll
        for (int i = 0; i < 4; ++i)
            a[i] = sA[(ty * 4 + i) * 64 + k4];
        #pragma unroll
        for (int jj = 0; jj < 8; ++jj) {
            float4 w = sW[k4 * SW_STRIDE + tx + 16 * jj];
            #pragma unroll
            for (int i = 0; i < 4; ++i) {
                c[i][jj] = fmaf(a[i].x, w.x, c[i][jj]);
                c[i][jj] = fmaf(a[i].y, w.y, c[i][jj]);
                c[i][jj] = fmaf(a[i].z, w.z, c[i][jj]);
                c[i][jj] = fmaf(a[i].w, w.w, c[i][jj]);
            }
        }
    }

    // --- Epilogue: out = x_i + b + c ---
    #pragma unroll
    for (int i = 0; i < 4; ++i) {
        int node = node0 + ty * 4 + i;
        if (node >= n_nodes) continue;
        #pragma unroll
        for (int jj = 0; jj < 8; ++jj) {
            int j = tx + 16 * jj;
            size_t idx = (size_t)node * FEAT + j;
            out[idx] = __ldg(x_i + idx) + __ldg(b + j) + c[i][jj];
        }
    }
}

// ---------------------------------------------------------------------------
// Launch
// inputs: [0] nbrs int32 [E,2], [1] x_i f32 [N,128], [2] scaled_v f32 [E,256],
//         [3] W f32 [128,256], [4] b f32 [128]
// ---------------------------------------------------------------------------
extern "C" void kernel_launch(void* const* d_in, const int* in_sizes, int n_in,
                              void* d_out, int out_size) {
    const int*   nbrs    = (const int*)d_in[0];
    const float* x_i     = (const float*)d_in[1];
    const float* scaledv = (const float*)d_in[2];
    const float* W       = (const float*)d_in[3];
    const float* b       = (const float*)d_in[4];
    float* out = (float*)d_out;

    const int n_edges = in_sizes[0] / 2;
    const int n_nodes = in_sizes[1] / FEAT;

    // Binning (atomic-free hot path afterwards)
    zero_cnt_kernel<<<(n_nodes + 255) / 256, 256>>>(n_nodes);
    hist_kernel<<<(n_edges + 255) / 256, 256>>>(nbrs, n_edges, n_nodes);
    scan_kernel<<<1, 1024>>>(n_nodes);
    fill_kernel<<<(n_edges + 255) / 256, 256>>>(nbrs, n_edges, n_nodes);

    // Fused gather + GEMM + residual
    size_t smem_bytes = (64 * SW_STRIDE + TILE_M * 64) * sizeof(float4);
    cudaFuncSetAttribute(fused_gemm_kernel,
                         cudaFuncAttributeMaxDynamicSharedMemorySize,
                         (int)smem_bytes);
    int gblocks = (n_nodes + TILE_M - 1) / TILE_M;
    fused_gemm_kernel<<<gblocks, 256, smem_bytes>>>(scaledv, x_i, W, b, out,
                                                    n_nodes);
}

// round 17
// speedup vs baseline: 1.6677x; 1.6677x over previous
#include <cuda_runtime.h>
#include <cstdint>

#define FEAT 128          // output feature dim
#define HF   256          // num_heads * feat_dim (accumulator width)
#define MAX_NODES 50000
#define MAX_EDGES 1000000

// Scratch
__device__ float g_acc[(size_t)MAX_NODES * HF];   // [N,256] gathered sums
__device__ int g_cnt[MAX_NODES];        // per-node edge count
__device__ int g_off[MAX_NODES + 1];    // exclusive offsets
__device__ int g_cur[MAX_NODES];        // running fill cursor
__device__ int g_eids[MAX_EDGES];       // edge ids bucketed by dst

// ---------------------------------------------------------------------------
// Kernel 0: zero per-node counters
// ---------------------------------------------------------------------------
__global__ void zero_cnt_kernel(int n_nodes) {
    int i = blockIdx.x * blockDim.x + threadIdx.x;
    if (i < n_nodes) g_cnt[i] = 0;
}

// ---------------------------------------------------------------------------
// Kernel 1: histogram of destinations
// ---------------------------------------------------------------------------
__global__ void hist_kernel(const int* __restrict__ nbrs, int n_edges, int n_nodes) {
    int e = blockIdx.x * blockDim.x + threadIdx.x;
    if (e >= n_edges) return;
    int dst = __ldg(nbrs + 2 * e);
    if ((unsigned)dst < (unsigned)n_nodes)
        atomicAdd(&g_cnt[dst], 1);
}

// ---------------------------------------------------------------------------
// Kernel 2: exclusive scan over g_cnt -> g_off, g_cur  (single block, 1024 thr)
// ---------------------------------------------------------------------------
__global__ void scan_kernel(int n_nodes) {
    __shared__ int part[1024];
    const int tid = threadIdx.x;
    const int per = (n_nodes + 1023) / 1024;
    const int start = tid * per;
    const int stop  = min(start + per, n_nodes);

    int s = 0;
    for (int i = start; i < stop; ++i) s += g_cnt[i];
    part[tid] = s;
    __syncthreads();

    for (int d = 1; d < 1024; d <<= 1) {
        int v = (tid >= d) ? part[tid - d] : 0;
        __syncthreads();
        part[tid] += v;
        __syncthreads();
    }

    int run = (tid == 0) ? 0 : part[tid - 1];
    for (int i = start; i < stop; ++i) {
        g_off[i] = run;
        g_cur[i] = run;
        run += g_cnt[i];
    }
    if (tid == 1023) g_off[n_nodes] = part[1023];
}

// ---------------------------------------------------------------------------
// Kernel 3: fill buckets with edge ids
// ---------------------------------------------------------------------------
__global__ void fill_kernel(const int* __restrict__ nbrs, int n_edges, int n_nodes) {
    int e = blockIdx.x * blockDim.x + threadIdx.x;
    if (e >= n_edges) return;
    int dst = __ldg(nbrs + 2 * e);
    if ((unsigned)dst >= (unsigned)n_nodes) return;
    int pos = atomicAdd(&g_cur[dst], 1);
    g_eids[pos] = e;
}

// ---------------------------------------------------------------------------
// Kernel 4: atomic-free gather. 4 nodes per 256-thread block; 64 threads per
// node, one float4 slot each. No smem -> full occupancy (64 warps/SM), and
// the inner loop is manually 4-wide so each thread keeps >=4 independent 16B
// loads in flight. Plain STG to g_acc (single writer per element).
// ---------------------------------------------------------------------------
__global__ void gather_kernel(const float* __restrict__ scaled_v, int n_nodes) {
    const int tid  = threadIdx.x;
    const int slot = tid & 63;               // float4 lane within 1KB row
    const int node = blockIdx.x * 4 + (tid >> 6);
    if (node >= n_nodes) return;

    const float4* sv4 = reinterpret_cast<const float4*>(scaled_v);
    const int beg = __ldg(&g_off[node]);
    const int end = __ldg(&g_off[node + 1]);

    float4 acc = make_float4(0.f, 0.f, 0.f, 0.f);
    int t = beg;
    for (; t + 4 <= end; t += 4) {
        int e0 = __ldg(&g_eids[t + 0]);
        int e1 = __ldg(&g_eids[t + 1]);
        int e2 = __ldg(&g_eids[t + 2]);
        int e3 = __ldg(&g_eids[t + 3]);
        float4 v0 = __ldg(sv4 + (size_t)e0 * 64 + slot);
        float4 v1 = __ldg(sv4 + (size_t)e1 * 64 + slot);
        float4 v2 = __ldg(sv4 + (size_t)e2 * 64 + slot);
        float4 v3 = __ldg(sv4 + (size_t)e3 * 64 + slot);
        acc.x += v0.x + v1.x + v2.x + v3.x;
        acc.y += v0.y + v1.y + v2.y + v3.y;
        acc.z += v0.z + v1.z + v2.z + v3.z;
        acc.w += v0.w + v1.w + v2.w + v3.w;
    }
    for (; t < end; ++t) {
        int e = __ldg(&g_eids[t]);
        float4 v = __ldg(sv4 + (size_t)e * 64 + slot);
        acc.x += v.x; acc.y += v.y; acc.z += v.z; acc.w += v.w;
    }

    reinterpret_cast<float4*>(g_acc)[(size_t)node * 64 + slot] = acc;
}

// ---------------------------------------------------------------------------
// Kernel 5: out[n, j] = x_i[n, j] + b[j] + sum_k acc[n, k] * W[j, k]
// (unchanged R10 tile kernel: 64 nodes x 128 outputs, conflict-free smem)
// ---------------------------------------------------------------------------
#define TILE_M 64
#define SW_STRIDE 129   // float4 units per k4-row of sW

__global__ void gemm_kernel(const float* __restrict__ x_i,
                            const float* __restrict__ W,
                            const float* __restrict__ b,
                            float*       __restrict__ out,
                            int n_nodes) {
    extern __shared__ float4 smem[];
    float4* sW = smem;                       // [64][SW_STRIDE]
    float4* sA = smem + 64 * SW_STRIDE;      // [TILE_M][64]

    const int tid = threadIdx.x;

    const float4* W4 = reinterpret_cast<const float4*>(W);
    #pragma unroll
    for (int it = 0; it < 32; ++it) {
        int g = tid + it * 256;
        int j  = g >> 6;
        int k4 = g & 63;
        sW[k4 * SW_STRIDE + j] = __ldg(W4 + g);
    }

    const int node0 = blockIdx.x * TILE_M;
    const float4* A4 = reinterpret_cast<const float4*>(g_acc);
    #pragma unroll
    for (int it = 0; it < 16; ++it) {
        int g = tid + it * 256;
        int n  = g >> 6;
        int k4 = g & 63;
        int node = node0 + n;
        sA[g] = (node < n_nodes) ? A4[(size_t)node * 64 + k4]
                                 : make_float4(0.f, 0.f, 0.f, 0.f);
    }
    __syncthreads();

    const int tx = tid & 15;
    const int ty = tid >> 4;

    float c[4][8];
    #pragma unroll
    for (int i = 0; i < 4; ++i)
        #pragma unroll
        for (int jj = 0; jj < 8; ++jj) c[i][jj] = 0.f;

    #pragma unroll 4
    for (int k4 = 0; k4 < 64; ++k4) {
        float4 a[4];
        #pragma unroll
        for (int i = 0; i < 4; ++i)
            a[i] = sA[(ty * 4 + i) * 64 + k4];
        #pragma unroll
        for (int jj = 0; jj < 8; ++jj) {
            float4 w = sW[k4 * SW_STRIDE + tx + 16 * jj];
            #pragma unroll
            for (int i = 0; i < 4; ++i) {
                c[i][jj] = fmaf(a[i].x, w.x, c[i][jj]);
                c[i][jj] = fmaf(a[i].y, w.y, c[i][jj]);
                c[i][jj] = fmaf(a[i].z, w.z, c[i][jj]);
                c[i][jj] = fmaf(a[i].w, w.w, c[i][jj]);
            }
        }
    }

    #pragma unroll
    for (int i = 0; i < 4; ++i) {
        int node = node0 + ty * 4 + i;
        if (node >= n_nodes) continue;
        #pragma unroll
        for (int jj = 0; jj < 8; ++jj) {
            int j = tx + 16 * jj;
            size_t idx = (size_t)node * FEAT + j;
            out[idx] = __ldg(x_i + idx) + __ldg(b + j) + c[i][jj];
        }
    }
}

// ---------------------------------------------------------------------------
// Launch
// inputs: [0] nbrs int32 [E,2], [1] x_i f32 [N,128], [2] scaled_v f32 [E,256],
//         [3] W f32 [128,256], [4] b f32 [128]
// ---------------------------------------------------------------------------
extern "C" void kernel_launch(void* const* d_in, const int* in_sizes, int n_in,
                              void* d_out, int out_size) {
    const int*   nbrs    = (const int*)d_in[0];
    const float* x_i     = (const float*)d_in[1];
    const float* scaledv = (const float*)d_in[2];
    const float* W       = (const float*)d_in[3];
    const float* b       = (const float*)d_in[4];
    float* out = (float*)d_out;

    const int n_edges = in_sizes[0] / 2;
    const int n_nodes = in_sizes[1] / FEAT;

    // Binning
    zero_cnt_kernel<<<(n_nodes + 255) / 256, 256>>>(n_nodes);
    hist_kernel<<<(n_edges + 255) / 256, 256>>>(nbrs, n_edges, n_nodes);
    scan_kernel<<<1, 1024>>>(n_nodes);
    fill_kernel<<<(n_edges + 255) / 256, 256>>>(nbrs, n_edges, n_nodes);

    // Atomic-free gather at full occupancy
    gather_kernel<<<(n_nodes + 3) / 4, 256>>>(scaledv, n_nodes);

    // GEMM + residual
    size_t smem_bytes = (64 * SW_STRIDE + TILE_M * 64) * sizeof(float4);
    cudaFuncSetAttribute(gemm_kernel,
                         cudaFuncAttributeMaxDynamicSharedMemorySize,
                         (int)smem_bytes);
    int gblocks = (n_nodes + TILE_M - 1) / TILE_M;
    gemm_kernel<<<gblocks, 256, smem_bytes>>>(x_i, W, b, out, n_nodes);
}